// round 3
// baseline (speedup 1.0000x reference)
#include <cuda_runtime.h>
#include <stdint.h>

// out[i] = in[i] + 0.1 * sqrt(2) * erfinv(u(i))
// Reproduces jax.random.normal(jax.random.key(42), (64,3,512,512), f32) under
// jax_threefry_partitionable=True (modern default):
//   per flat element i (< 2^32):
//     (y0, y1) = threefry2x32(key=(0,42), counts=(i>>32 = 0, i & 0xffffffff))
//     bits32   = y0 ^ y1            // prng.py: convert(bits1 ^ bits2, u32)
//   f = bitcast((bits>>9)|0x3F800000) - 1          in [0,1)
//   u = max(LO, f*2 + LO),  LO = nextafter(-1,0) = -0.99999994f
//     (maxval-minval = 1-LO rounds to exactly 2.0f)
//   normal = sqrt(2)*erfinv(u)   [XLA Giles polynomial]

#define TF_K0 0u
#define TF_K1 42u
#define TF_K2 (0x1BD11BDAu ^ TF_K0 ^ TF_K1)   // 0x1BD11BF0

// Full 20-round threefry2x32 on (x0=0, x1=i); returns XOR of final lanes.
__device__ __forceinline__ uint32_t threefry_xor(uint32_t x0, uint32_t x1) {
#define TF_RND(r) { x0 += x1; x1 = __funnelshift_l(x1, x1, (r)); x1 ^= x0; }
    x0 += TF_K0; x1 += TF_K1;
    TF_RND(13) TF_RND(15) TF_RND(26) TF_RND(6)
    x0 += TF_K1; x1 += TF_K2 + 1u;
    TF_RND(17) TF_RND(29) TF_RND(16) TF_RND(24)
    x0 += TF_K2; x1 += TF_K0 + 2u;
    TF_RND(13) TF_RND(15) TF_RND(26) TF_RND(6)
    x0 += TF_K0; x1 += TF_K1 + 3u;
    TF_RND(17) TF_RND(29) TF_RND(16) TF_RND(24)
    x0 += TF_K1; x1 += TF_K2 + 4u;
    TF_RND(13) TF_RND(15) TF_RND(26) TF_RND(6)
    x0 += TF_K2; x1 += TF_K0 + 5u;
#undef TF_RND
    return x0 ^ x1;
}

// 0.1 * sqrt(2) * erfinv(u) from raw bits, XLA float32 erf_inv (Giles) poly.
__device__ __forceinline__ float bits_to_noise(uint32_t b) {
    const float LO = -0.99999994f;  // nextafter(-1, 0)
    float f = __uint_as_float((b >> 9) | 0x3F800000u) - 1.0f;
    float u = fmaf(f, 2.0f, LO);
    u = fmaxf(LO, u);

    float w = -__logf(fmaf(-u, u, 1.0f));   // -log(1 - u*u)
    float p;
    if (w < 5.0f) {
        w = w - 2.5f;
        p =              2.81022636e-08f;
        p = fmaf(p, w,   3.43273939e-07f);
        p = fmaf(p, w,  -3.5233877e-06f);
        p = fmaf(p, w,  -4.39150654e-06f);
        p = fmaf(p, w,   0.00021858087f);
        p = fmaf(p, w,  -0.00125372503f);
        p = fmaf(p, w,  -0.00417768164f);
        p = fmaf(p, w,   0.246640727f);
        p = fmaf(p, w,   1.50140941f);
    } else {
        w = sqrtf(w) - 3.0f;
        p =             -0.000200214257f;
        p = fmaf(p, w,   0.000100950558f);
        p = fmaf(p, w,   0.00134934322f);
        p = fmaf(p, w,  -0.00367342844f);
        p = fmaf(p, w,   0.00573950773f);
        p = fmaf(p, w,  -0.0076224613f);
        p = fmaf(p, w,   0.00943887047f);
        p = fmaf(p, w,   1.00167406f);
        p = fmaf(p, w,   2.83297682f);
    }
    // 0.1 * sqrt(2) * erfinv(u);  erfinv(u) = p * u
    return 0.14142136f * (p * u);
}

// Thread t handles elements [4t, 4t+4): one float4 load + one float4 store,
// 4 independent threefry chains for ILP.
__global__ void __launch_bounds__(256)
noise_vec_kernel(const float4* __restrict__ in, float4* __restrict__ out,
                 int n4) {
    int t = blockIdx.x * blockDim.x + threadIdx.x;
    if (t >= n4) return;

    float4 a = in[t];
    unsigned int c = 4u * (unsigned int)t;

    uint32_t b0 = threefry_xor(0u, c + 0u);
    uint32_t b1 = threefry_xor(0u, c + 1u);
    uint32_t b2 = threefry_xor(0u, c + 2u);
    uint32_t b3 = threefry_xor(0u, c + 3u);

    float4 r;
    r.x = a.x + bits_to_noise(b0);
    r.y = a.y + bits_to_noise(b1);
    r.z = a.z + bits_to_noise(b2);
    r.w = a.w + bits_to_noise(b3);

    out[t] = r;
}

// Scalar tail (not hit for this shape; kept for safety).
__global__ void noise_tail_kernel(const float* __restrict__ in,
                                  float* __restrict__ out,
                                  unsigned int start, unsigned int n) {
    unsigned int i = start + blockIdx.x * blockDim.x + threadIdx.x;
    if (i >= n) return;
    out[i] = in[i] + bits_to_noise(threefry_xor(0u, i));
}

extern "C" void kernel_launch(void* const* d_in, const int* in_sizes, int n_in,
                              void* d_out, int out_size) {
    const float* in = (const float*)d_in[0];
    float* out = (float*)d_out;

    unsigned int n = (unsigned int)in_sizes[0];  // 50331648
    int n4 = (int)(n / 4u);                      // 12582912

    if (n4 > 0) {
        int threads = 256;
        int blocks = (n4 + threads - 1) / threads;
        noise_vec_kernel<<<blocks, threads>>>((const float4*)in, (float4*)out, n4);
    }
    unsigned int done = (unsigned int)n4 * 4u;
    if (done < n) {
        unsigned int rem = n - done;
        noise_tail_kernel<<<(rem + 255) / 256, 256>>>(in, out, done, n);
    }
}

// round 4
// speedup vs baseline: 1.0027x; 1.0027x over previous
#include <cuda_runtime.h>
#include <stdint.h>

// out[i] = in[i] + 0.1*sqrt(2)*erfinv(u(i)), matching
// jax.random.normal(jax.random.key(42), (64,3,512,512), f32) with
// jax_threefry_partitionable=True:
//   (y0,y1) = threefry2x32((0,42), (0, i));  bits = y0 ^ y1
//   f = bitcast((bits>>9)|0x3F800000)-1;  u = fma(f, 2.0f, LO), LO=-0.99999994
//   noise = 0.1*sqrt(2)*erfinv(u)   [XLA Giles poly; scale folded into coeffs]
//
// Perf: threefry x0-lane adds + key injections forced onto the FMA pipe via
// mad.lo.u32 with an opaque 'one' register -> alu/fma pipes balanced.

__device__ __forceinline__ uint32_t mad1(uint32_t a, uint32_t b, uint32_t c) {
    uint32_t d;
    asm("mad.lo.u32 %0, %1, %2, %3;" : "=r"(d) : "r"(a), "r"(b), "r"(c));
    return d;
}

// 20-round threefry2x32 on (0, ctr); returns x0^x1.
// 'one' == 1 (opaque). k* are warp-uniform key-schedule constants in regs.
__device__ __forceinline__ uint32_t tf_xor(uint32_t ctr, uint32_t one,
                                           uint32_t k1, uint32_t k2,
                                           uint32_t k2p1, uint32_t c2,
                                           uint32_t k1p3, uint32_t k2p4,
                                           uint32_t c5) {
#define TF_RND(r) { x0 = mad1(x1, one, x0); \
                    x1 = __funnelshift_l(x1, x1, (r)); x1 ^= x0; }
    uint32_t x0 = 0u;                 // key k0 = 0
    uint32_t x1 = mad1(one, k1, ctr); // inj0: x1 += 42
    TF_RND(13) TF_RND(15) TF_RND(26) TF_RND(6)
    x0 = mad1(one, k1, x0);  x1 = mad1(one, k2p1, x1);
    TF_RND(17) TF_RND(29) TF_RND(16) TF_RND(24)
    x0 = mad1(one, k2, x0);  x1 = mad1(one, c2, x1);
    TF_RND(13) TF_RND(15) TF_RND(26) TF_RND(6)
    /* x0 += k0 = 0 */       x1 = mad1(one, k1p3, x1);
    TF_RND(17) TF_RND(29) TF_RND(16) TF_RND(24)
    x0 = mad1(one, k1, x0);  x1 = mad1(one, k2p4, x1);
    TF_RND(13) TF_RND(15) TF_RND(26) TF_RND(6)
    x0 = mad1(one, k2, x0);  x1 = mad1(one, c5, x1);
#undef TF_RND
    return x0 ^ x1;
}

// bits -> u in [LO, 1), LO = nextafter(-1,0). (fmax(LO,.) is a no-op: f>=0.)
__device__ __forceinline__ float bits_to_u(uint32_t b) {
    float f = __uint_as_float((b >> 9) | 0x3F800000u) - 1.0f;
    return fmaf(f, 2.0f, -0.99999994f);
}

// Giles erfinv polys with 0.1*sqrt(2) folded into the coefficients.
// Returns the full noise value (= 0.14142136 * erfinv(u)).
__device__ __forceinline__ float noise_small(float w, float u) {
    w = w - 2.5f;
    float p =        3.97427254e-09f;
    p = fmaf(p, w,   4.85464967e-08f);
    p = fmaf(p, w,  -4.98283055e-07f);
    p = fmaf(p, w,  -6.21053463e-07f);
    p = fmaf(p, w,   3.09122925e-05f);
    p = fmaf(p, w,  -1.77302644e-04f);
    p = fmaf(p, w,  -5.90813690e-04f);
    p = fmaf(p, w,   3.48802861e-02f);
    p = fmaf(p, w,   2.12331951e-01f);
    return p * u;
}
__device__ __forceinline__ float noise_tail(float w, float u) {
    w = sqrtf(w) - 3.0f;
    float p =       -2.83145467e-05f;
    p = fmaf(p, w,   1.42766481e-05f);
    p = fmaf(p, w,   1.90824894e-04f);
    p = fmaf(p, w,  -5.19499916e-04f);
    p = fmaf(p, w,   8.11690563e-04f);
    p = fmaf(p, w,  -1.07798485e-03f);
    p = fmaf(p, w,   1.33486521e-03f);
    p = fmaf(p, w,   1.41657794e-01f);
    p = fmaf(p, w,   4.00644237e-01f);
    return p * u;
}

__global__ void __launch_bounds__(256)
noise_vec_kernel(const float4* __restrict__ in, float4* __restrict__ out,
                 int n4, uint32_t one) {
    int t = blockIdx.x * blockDim.x + threadIdx.x;
    if (t >= n4) return;

    // Warp-uniform key-schedule constants, kept opaque via 'one'.
    const uint32_t k1   = 42u * one;
    const uint32_t k2   = 0x1BD11BF0u * one;     // 0x1BD11BDA ^ 0 ^ 42
    const uint32_t k2p1 = k2 + 1u;
    const uint32_t c2   = 2u * one;
    const uint32_t k1p3 = k1 + 3u;
    const uint32_t k2p4 = k2 + 4u;
    const uint32_t c5   = 5u * one;

    float4 a = in[t];
    unsigned int c = 4u * (unsigned int)t;

    uint32_t b0 = tf_xor(c + 0u, one, k1, k2, k2p1, c2, k1p3, k2p4, c5);
    uint32_t b1 = tf_xor(c + 1u, one, k1, k2, k2p1, c2, k1p3, k2p4, c5);
    uint32_t b2 = tf_xor(c + 2u, one, k1, k2, k2p1, c2, k1p3, k2p4, c5);
    uint32_t b3 = tf_xor(c + 3u, one, k1, k2, k2p1, c2, k1p3, k2p4, c5);

    float u0 = bits_to_u(b0), u1 = bits_to_u(b1);
    float u2 = bits_to_u(b2), u3 = bits_to_u(b3);

    float w0 = -__logf(fmaf(-u0, u0, 1.0f));
    float w1 = -__logf(fmaf(-u1, u1, 1.0f));
    float w2 = -__logf(fmaf(-u2, u2, 1.0f));
    float w3 = -__logf(fmaf(-u3, u3, 1.0f));

    float r0 = noise_small(w0, u0);
    float r1 = noise_small(w1, u1);
    float r2 = noise_small(w2, u2);
    float r3 = noise_small(w3, u3);

    // Rare tail (|u| > 0.99663): one branch per thread.
    if (!(w0 < 5.0f && w1 < 5.0f && w2 < 5.0f && w3 < 5.0f)) {
        if (w0 >= 5.0f) r0 = noise_tail(w0, u0);
        if (w1 >= 5.0f) r1 = noise_tail(w1, u1);
        if (w2 >= 5.0f) r2 = noise_tail(w2, u2);
        if (w3 >= 5.0f) r3 = noise_tail(w3, u3);
    }

    float4 r;
    r.x = a.x + r0;
    r.y = a.y + r1;
    r.z = a.z + r2;
    r.w = a.w + r3;
    out[t] = r;
}

// Scalar tail (not hit for this shape; kept for safety).
__global__ void noise_tail_kernel(const float* __restrict__ in,
                                  float* __restrict__ out,
                                  unsigned int start, unsigned int n,
                                  uint32_t one) {
    unsigned int i = start + blockIdx.x * blockDim.x + threadIdx.x;
    if (i >= n) return;
    const uint32_t k1 = 42u * one, k2 = 0x1BD11BF0u * one;
    uint32_t b = tf_xor(i, one, k1, k2, k2 + 1u, 2u * one, k1 + 3u, k2 + 4u,
                        5u * one);
    float u = bits_to_u(b);
    float w = -__logf(fmaf(-u, u, 1.0f));
    float r = (w < 5.0f) ? noise_small(w, u) : noise_tail(w, u);
    out[i] = in[i] + r;
}

extern "C" void kernel_launch(void* const* d_in, const int* in_sizes, int n_in,
                              void* d_out, int out_size) {
    const float* in = (const float*)d_in[0];
    float* out = (float*)d_out;

    unsigned int n = (unsigned int)in_sizes[0];  // 50331648
    int n4 = (int)(n / 4u);                      // 12582912

    if (n4 > 0) {
        int threads = 256;
        int blocks = (n4 + threads - 1) / threads;
        noise_vec_kernel<<<blocks, threads>>>((const float4*)in, (float4*)out,
                                              n4, 1u);
    }
    unsigned int done = (unsigned int)n4 * 4u;
    if (done < n) {
        unsigned int rem = n - done;
        noise_tail_kernel<<<(rem + 255) / 256, 256>>>(in, out, done, n, 1u);
    }
}